// round 16
// baseline (speedup 1.0000x reference)
#include <cuda_runtime.h>
#include <cuda_bf16.h>

// ---------------------------------------------------------------------------
// Problem constants (fixed shapes)
constexpr int B    = 4;
constexpr int NPTS = 4096;
constexpr int MPTS = 4096;
constexpr int C    = 128;
constexpr int KNN  = 32;
constexpr float RAD2 = 0.12f * 0.12f;
constexpr int GC   = 8;          // grid cells per dim (cell 0.125 > r 0.12)
constexpr int NC   = GC*GC*GC;   // 512 cells per batch
constexpr float LOG2E = 1.4426950408889634f;

// Scratch (__device__ globals; allocation-free rule)
__device__ __align__(16) float g_QA[B*NPTS*C];    // EQ = exp2(a@Wqa+bqa)
__device__ __align__(16) float g_AD[B*NPTS*C];    // a@Wd + bd
__device__ __align__(16) float g_KN[B*MPTS*2*C];  // row m: [EK = exp2(-ka) | n@Wd]

// Precomputed folded weights
__device__ float g_Wqa[3*C];
__device__ float g_Wka[3*C];
__device__ float g_bqa[C];

// Spatial grid: set 0 = anchors, set 1 = neighbors. Index = (set*4+b)*NC + cell.
__device__ int    g_cnt  [2*B*NC];
__device__ int    g_start[2*B*NC];
__device__ __align__(16) float4 g_pts[2*B*4096];  // cell-sorted (x,y,z,idx)

// Ball query results, indexed by cell-sorted anchor position p (coalesced).
__device__ int g_idx [B*NPTS*KNN];
__device__ int g_take[B*NPTS];

__device__ __forceinline__ float ex2f(float x) {
    float r; asm("ex2.approx.f32 %0, %1;" : "=f"(r) : "f"(x)); return r;
}
__device__ __forceinline__ float rcpf(float x) {
    float r; asm("rcp.approx.f32 %0, %1;" : "=f"(r) : "f"(x)); return r;
}
__device__ __forceinline__ int redux_min_s32(int v) {
    int r; asm("redux.sync.min.s32 %0, %1, 0xffffffff;" : "=r"(r) : "r"(v));
    return r;
}

__device__ __forceinline__ void cell_coords(float x, float y, float z,
                                            int& cx, int& cy, int& cz) {
    cx = min(GC-1, max(0, (int)(x * (float)GC)));
    cy = min(GC-1, max(0, (int)(y * (float)GC)));
    cz = min(GC-1, max(0, (int)(z * (float)GC)));
}

// ---------------------------------------------------------------------------
// Weight folding, k-split over 4 groups: thread (g, c) accumulates k in
// [g*32, g*32+32); 4 partials reduced via smem. ~1.5us (vs 6+ serial).
// ---------------------------------------------------------------------------
__global__ void __launch_bounds__(512)
fold_kernel(const float* __restrict__ Wq,
            const float* __restrict__ bq,
            const float* __restrict__ Wk,
            const float* __restrict__ bk,
            const float* __restrict__ Wa,
            const float* __restrict__ ba)
{
    __shared__ float s_wq[3*C], s_wk[3*C], s_bqk[C];
    __shared__ float s_part[4][7*C];     // [group][output*C + c]

    const int t = threadIdx.x;
    if (t < 3*C) { s_wq[t] = Wq[t]; s_wk[t] = Wk[t]; }
    if (t < C)   s_bqk[t] = bq[t] - bk[t];
    __syncthreads();

    const int c = t & 127;
    const int g = t >> 7;

    float aq0=0.f, aq1=0.f, aq2=0.f, ak0=0.f, ak1=0.f, ak2=0.f, ab=0.f;
#pragma unroll 8
    for (int kk = 0; kk < 32; ++kk) {
        const int k = g * 32 + kk;
        const float w = Wa[k*C + c];     // coalesced per group
        aq0 += s_wq[k      ] * w;
        aq1 += s_wq[C   + k] * w;
        aq2 += s_wq[2*C + k] * w;
        ak0 += s_wk[k      ] * w;
        ak1 += s_wk[C   + k] * w;
        ak2 += s_wk[2*C + k] * w;
        ab  += s_bqk[k] * w;
    }
    s_part[g][0*C+c]=aq0; s_part[g][1*C+c]=aq1; s_part[g][2*C+c]=aq2;
    s_part[g][3*C+c]=ak0; s_part[g][4*C+c]=ak1; s_part[g][5*C+c]=ak2;
    s_part[g][6*C+c]=ab;
    __syncthreads();

    if (t < C) {
        float r[7];
#pragma unroll
        for (int j = 0; j < 7; ++j)
            r[j] = (s_part[0][j*C+t] + s_part[1][j*C+t])
                 + (s_part[2][j*C+t] + s_part[3][j*C+t]);
        g_Wqa[t] = r[0]*LOG2E; g_Wqa[C+t] = r[1]*LOG2E; g_Wqa[2*C+t] = r[2]*LOG2E;
        g_Wka[t] = r[3]*LOG2E; g_Wka[C+t] = r[4]*LOG2E; g_Wka[2*C+t] = r[5]*LOG2E;
        g_bqa[t] = (r[6] + ba[t]) * LOG2E;
    }
}

// ---------------------------------------------------------------------------
// Streaming projections: blocks [0,512) anchors, [512,1024) neighbors,
// 32 rows per block, 256 threads. anchors: g_QA = EQ = exp2(qa);
// neighbors: g_KN = [EK = exp2(-ka) | ND].
// ---------------------------------------------------------------------------
__global__ void __launch_bounds__(256)
proj_kernel(const float* __restrict__ anchor,
            const float* __restrict__ neighbor,
            const float* __restrict__ Wd,
            const float* __restrict__ bd)
{
    constexpr int TR = 32;
    __shared__ float p_s[TR * 3];

    const bool AN = blockIdx.x < 512;
    const int  base_row = (AN ? blockIdx.x : blockIdx.x - 512) * TR;
    const float* xyz = AN ? anchor : neighbor;
    const int t = threadIdx.x;

    if (t < TR * 3) p_s[t] = xyz[(size_t)base_row * 3 + t];
    __syncthreads();

    const int c = t & 127;
    const int h = t >> 7;
    const float* WA = AN ? g_Wqa : g_Wka;
    const float wax = WA[c], way = WA[C + c], waz = WA[2*C + c];
    const float wdx = Wd[c], wdy = Wd[C + c], wdz = Wd[2*C + c];
    const float ab = AN ? g_bqa[c] : 0.0f;
    const float db = AN ? bd[c]    : 0.0f;

#pragma unroll
    for (int r = 0; r < 16; ++r) {
        const int rr = h * 16 + r;
        const float x = p_s[rr*3], y = p_s[rr*3+1], z = p_s[rr*3+2];
        const float a = ab + x*wax + y*way + z*waz;
        const float d = db + x*wdx + y*wdy + z*wdz;
        const int row = base_row + rr;
        if (AN) {
            g_QA[(size_t)row * C + c] = ex2f(a);            // EQ factor
            g_AD[(size_t)row * C + c] = d;
        } else {
            g_KN[(size_t)row * (2*C) + c]     = ex2f(-a);   // EK factor
            g_KN[(size_t)row * (2*C) + C + c] = d;
        }
    }
}

// ---------------------------------------------------------------------------
// Grid build: one block per (set, batch). 512 threads, 4096 points.
// Emits g_pts: cell-sorted float4(x, y, z, local_idx).
// ---------------------------------------------------------------------------
__global__ void __launch_bounds__(512)
gridbuild_kernel(const float* __restrict__ anchor,
                 const float* __restrict__ neighbor)
{
    __shared__ int s_cnt [NC];
    __shared__ int s_scan[NC];
    __shared__ int s_cur [NC];
    __shared__ int s_cell[4096];

    const int bi  = blockIdx.x;          // set*4 + b
    const int set = bi >> 2;
    const int b   = bi & 3;
    const float* pts = (set ? neighbor : anchor) + (size_t)b * 4096 * 3;
    const int t = threadIdx.x;

    s_cnt[t] = 0;
    __syncthreads();

#pragma unroll
    for (int r = 0; r < 8; ++r) {
        const int i = t + r * 512;
        const float x = pts[i*3], y = pts[i*3+1], z = pts[i*3+2];
        int cx, cy, cz; cell_coords(x, y, z, cx, cy, cz);
        const int c = cz*64 + cy*8 + cx;
        s_cell[i] = c;
        atomicAdd(&s_cnt[c], 1);
    }
    __syncthreads();

    const int cval = s_cnt[t];
    s_scan[t] = cval;
    __syncthreads();
    for (int off = 1; off < NC; off <<= 1) {
        const int v = (t >= off) ? s_scan[t - off] : 0;
        __syncthreads();
        s_scan[t] += v;
        __syncthreads();
    }
    const int start = s_scan[t] - cval;
    g_cnt  [bi*NC + t] = cval;
    g_start[bi*NC + t] = start;
    s_cur[t] = start;
    __syncthreads();

#pragma unroll
    for (int r = 0; r < 8; ++r) {
        const int i = t + r * 512;
        const float x = pts[i*3], y = pts[i*3+1], z = pts[i*3+2];  // L1 hit
        const int slot = atomicAdd(&s_cur[s_cell[i]], 1);
        g_pts[bi*4096 + slot] = make_float4(x, y, z, __int_as_float(i));
    }
}

// ---------------------------------------------------------------------------
// Ball query. Warp per anchor (cell-sorted p). Depends only on gridbuild,
// so it overlaps proj on the other stream. Writes g_idx[p*32+lane] and
// g_take[p] (rounded up to x4; padding slots are harmless duplicates).
// ---------------------------------------------------------------------------
__global__ void __launch_bounds__(256)
ballquery_kernel()
{
    constexpr unsigned FULL = 0xffffffffu;
    constexpr int CAP = 128;
    __shared__ int hbuf[8][CAP];
    __shared__ int sorted[8][KNN];

    const int warp = threadIdx.x >> 5;
    const int lane = threadIdx.x & 31;
    const int p    = blockIdx.x * 8 + warp;
    const int b    = p >> 12;

    const float4 a4 = g_pts[p];
    const float ax = a4.x, ay = a4.y, az = a4.z;
    int cx, cy, cz; cell_coords(ax, ay, az, cx, cy, cz);

    const int nbase = (B + b) * NC;
    const float4* cand = g_pts + (B + b) * 4096;

    const int x0 = max(cx - 1, 0), x1 = min(cx + 1, GC - 1);

    // Phase 0: parallel span-descriptor fetch (lanes 0..8)
    int stv = 0, env = 0;
    if (lane < 9) {
        const int z = cz - 1 + lane / 3;
        const int y = cy - 1 + lane % 3;
        if ((unsigned)z < (unsigned)GC && (unsigned)y < (unsigned)GC) {
            const int cA = nbase + z*64 + y*8 + x0;
            const int cB = nbase + z*64 + y*8 + x1;
            stv = g_start[cA];
            env = g_start[cB] + g_cnt[cB];
        }
    }

    // Phase 1: collect hits
    int hcnt = 0;
#pragma unroll
    for (int i = 0; i < 9; ++i) {
        const int st = __shfl_sync(FULL, stv, i);
        const int en = __shfl_sync(FULL, env, i);
        for (int j = st; j < en; j += 32) {
            const int q = j + lane;
            int m = 0; bool hit = false;
            if (q < en) {
                const float4 c4 = cand[q];       // coalesced LDG.128
                const float fx = c4.x - ax;
                const float fy = c4.y - ay;
                const float fz = c4.z - az;
                hit = (fx*fx + fy*fy + fz*fz) < RAD2;
                m = __float_as_int(c4.w);
            }
            const unsigned mk = __ballot_sync(FULL, hit);
            if (hit) {
                const int pos = hcnt + __popc(mk & ((1u << lane) - 1u));
                if (pos < CAP) hbuf[warp][pos] = m;
            }
            hcnt += __popc(mk);
        }
    }
    __syncwarp(FULL);

    // Phase 2: slot selection
    int my_m;
    if (hcnt <= KNN) {
        const int v = (lane < hcnt) ? hbuf[warp][lane] : 0x7fffffff;
        const int mn = redux_min_s32(v);
        my_m = (lane < hcnt) ? v : ((hcnt > 0) ? mn : 0);
    } else {
        const int n = min(hcnt, CAP);
        const int rounds = (n + 31) >> 5;
        int v[4], rk[4];
#pragma unroll
        for (int r = 0; r < 4; ++r) {
            const int i = lane + 32*r;
            v[r]  = (i < n) ? hbuf[warp][i] : 0x7fffffff;
            rk[r] = 0;
        }
        for (int step = 0; step < 32; ++step) {
#pragma unroll
            for (int s = 0; s < 4; ++s) {
                if (s < rounds) {
                    const int u = __shfl_sync(FULL, v[s], step);
#pragma unroll
                    for (int r = 0; r < 4; ++r)
                        if (r < rounds) rk[r] += (u < v[r]);
                }
            }
        }
#pragma unroll
        for (int r = 0; r < 4; ++r) {
            const int i = lane + 32*r;
            if (i < n && rk[r] < KNN) sorted[warp][rk[r]] = v[r];
        }
        __syncwarp(FULL);
        my_m = sorted[warp][lane];
    }

    g_idx[(size_t)p * KNN + lane] = my_m;
    if (lane == 0) {
        const int t0 = (hcnt == 0) ? 1 : min(hcnt, KNN);
        g_take[p] = min((t0 + 3) & ~3, KNN);    // x4-rounded; dups harmless
    }
}

// ---------------------------------------------------------------------------
// Attention. Warp per anchor (cell-sorted p). take is a multiple of 4;
// hand-unrolled x4, no remainder. s = dot(EQ, EK_row) via FMA chain;
// EQ deferred to the epilogue (positive, constant over k).
// ---------------------------------------------------------------------------
__global__ void __launch_bounds__(256)
attn_kernel(float* __restrict__ out)
{
    constexpr unsigned FULL = 0xffffffffu;
    const int warp = threadIdx.x >> 5;
    const int lane = threadIdx.x & 31;
    const int p    = blockIdx.x * 8 + warp;
    const int b    = p >> 12;

    const int row  = (b << 12) + __float_as_int(g_pts[p].w);
    const int my_m = g_idx[(size_t)p * KNN + lane];
    const int take = g_take[p];

    const float4 eqv = ((const float4*)(g_QA + (size_t)row * C))[lane];  // EQ
    const float4 ad  = ((const float4*)(g_AD + (size_t)row * C))[lane];
    const float* KNb = g_KN + (size_t)b * MPTS * (2*C);

    float4 o = make_float4(-3.4e38f, -3.4e38f, -3.4e38f, -3.4e38f);

    for (int k = 0; k < take; k += 4) {
#pragma unroll
        for (int u = 0; u < 4; ++u) {
            const int m = __shfl_sync(FULL, my_m, k + u);
            const float4* base = (const float4*)(KNb + (size_t)m * (2*C));
            const float4 kv = base[lane];        // EK factors
            const float4 nv = base[32 + lane];   // ND

            float s = fmaf(eqv.x, kv.x,
                      fmaf(eqv.y, kv.y,
                      fmaf(eqv.z, kv.z, eqv.w * kv.w)));
#pragma unroll
            for (int off = 16; off; off >>= 1)
                s += __shfl_xor_sync(FULL, s, off);

            const float inv = rcpf(s);
            o.x = fmaxf(o.x, (ad.x - nv.x) * kv.x * inv);
            o.y = fmaxf(o.y, (ad.y - nv.y) * kv.y * inv);
            o.z = fmaxf(o.z, (ad.z - nv.z) * kv.z * inv);
            o.w = fmaxf(o.w, (ad.w - nv.w) * kv.w * inv);
        }
    }

    o.x *= eqv.x; o.y *= eqv.y; o.z *= eqv.z; o.w *= eqv.w;
    ((float4*)(out + (size_t)row * C))[lane] = o;
}

// ---------------------------------------------------------------------------
// Launch graph:
//   side : fold -> proj ────────────┐
//   main : gridbuild -> ballquery ──┴→ attn
// ballquery overlaps fold+proj; attn waits on both.
// ---------------------------------------------------------------------------
extern "C" void kernel_launch(void* const* d_in, const int* in_sizes, int n_in,
                              void* d_out, int out_size)
{
    const float* anchor   = (const float*)d_in[0];
    const float* neighbor = (const float*)d_in[1];
    const float* Wq = (const float*)d_in[2];
    const float* bq = (const float*)d_in[3];
    const float* Wk = (const float*)d_in[4];
    const float* bk = (const float*)d_in[5];
    const float* Wd = (const float*)d_in[6];
    const float* bd = (const float*)d_in[7];
    const float* Wa = (const float*)d_in[8];
    const float* ba = (const float*)d_in[9];
    float* out = (float*)d_out;

    static cudaStream_t s_side = nullptr;
    static cudaEvent_t  e_fork = nullptr, e_join = nullptr;
    if (s_side == nullptr) {
        cudaStreamCreateWithFlags(&s_side, cudaStreamNonBlocking);
        cudaEventCreateWithFlags(&e_fork, cudaEventDisableTiming);
        cudaEventCreateWithFlags(&e_join, cudaEventDisableTiming);
    }

    cudaEventRecord(e_fork, 0);
    cudaStreamWaitEvent(s_side, e_fork, 0);
    fold_kernel<<<1, 512, 0, s_side>>>(Wq, bq, Wk, bk, Wa, ba);
    proj_kernel<<<1024, 256, 0, s_side>>>(anchor, neighbor, Wd, bd);
    cudaEventRecord(e_join, s_side);

    gridbuild_kernel<<<8, 512>>>(anchor, neighbor);
    ballquery_kernel<<<2048, 256>>>();

    cudaStreamWaitEvent(0, e_join, 0);
    attn_kernel<<<2048, 256>>>(out);
}

// round 17
// speedup vs baseline: 1.1098x; 1.1098x over previous
#include <cuda_runtime.h>
#include <cuda_bf16.h>

// ---------------------------------------------------------------------------
// Problem constants (fixed shapes)
constexpr int B    = 4;
constexpr int NPTS = 4096;
constexpr int MPTS = 4096;
constexpr int C    = 128;
constexpr int KNN  = 32;
constexpr float RAD2 = 0.12f * 0.12f;
constexpr int GC   = 8;          // grid cells per dim (cell 0.125 > r 0.12)
constexpr int NC   = GC*GC*GC;   // 512 cells per batch
constexpr float LOG2E = 1.4426950408889634f;

// Scratch (__device__ globals; allocation-free rule)
__device__ __align__(16) float g_QA[B*NPTS*C];    // EQ = exp2(a@Wqa+bqa)
__device__ __align__(16) float g_AD[B*NPTS*C];    // a@Wd + bd
__device__ __align__(16) float g_KN[B*MPTS*2*C];  // row m: [EK = exp2(-ka) | n@Wd]

// Precomputed folded weights
__device__ float g_Wqa[3*C];
__device__ float g_Wka[3*C];
__device__ float g_bqa[C];

// Spatial grid: set 0 = anchors, set 1 = neighbors. Index = (set*4+b)*NC + cell.
__device__ int    g_cnt  [2*B*NC];
__device__ int    g_start[2*B*NC];
__device__ __align__(16) float4 g_pts[2*B*4096];  // cell-sorted (x,y,z,idx)

__device__ __forceinline__ float ex2f(float x) {
    float r; asm("ex2.approx.f32 %0, %1;" : "=f"(r) : "f"(x)); return r;
}
__device__ __forceinline__ float rcpf(float x) {
    float r; asm("rcp.approx.f32 %0, %1;" : "=f"(r) : "f"(x)); return r;
}
__device__ __forceinline__ int redux_min_s32(int v) {
    int r; asm("redux.sync.min.s32 %0, %1, 0xffffffff;" : "=r"(r) : "r"(v));
    return r;
}

__device__ __forceinline__ void cell_coords(float x, float y, float z,
                                            int& cx, int& cy, int& cz) {
    cx = min(GC-1, max(0, (int)(x * (float)GC)));
    cy = min(GC-1, max(0, (int)(y * (float)GC)));
    cz = min(GC-1, max(0, (int)(z * (float)GC)));
}

// ---------------------------------------------------------------------------
// Weight folding, k-split over 4 groups: thread (g, c) accumulates k in
// [g*32, g*32+32); 4 partials reduced via smem. ~2us.
// ---------------------------------------------------------------------------
__global__ void __launch_bounds__(512)
fold_kernel(const float* __restrict__ Wq,
            const float* __restrict__ bq,
            const float* __restrict__ Wk,
            const float* __restrict__ bk,
            const float* __restrict__ Wa,
            const float* __restrict__ ba)
{
    __shared__ float s_wq[3*C], s_wk[3*C], s_bqk[C];
    __shared__ float s_part[4][7*C];     // [group][output*C + c]

    const int t = threadIdx.x;
    if (t < 3*C) { s_wq[t] = Wq[t]; s_wk[t] = Wk[t]; }
    if (t < C)   s_bqk[t] = bq[t] - bk[t];
    __syncthreads();

    const int c = t & 127;
    const int g = t >> 7;

    float aq0=0.f, aq1=0.f, aq2=0.f, ak0=0.f, ak1=0.f, ak2=0.f, ab=0.f;
#pragma unroll 8
    for (int kk = 0; kk < 32; ++kk) {
        const int k = g * 32 + kk;
        const float w = Wa[k*C + c];     // coalesced per group
        aq0 += s_wq[k      ] * w;
        aq1 += s_wq[C   + k] * w;
        aq2 += s_wq[2*C + k] * w;
        ak0 += s_wk[k      ] * w;
        ak1 += s_wk[C   + k] * w;
        ak2 += s_wk[2*C + k] * w;
        ab  += s_bqk[k] * w;
    }
    s_part[g][0*C+c]=aq0; s_part[g][1*C+c]=aq1; s_part[g][2*C+c]=aq2;
    s_part[g][3*C+c]=ak0; s_part[g][4*C+c]=ak1; s_part[g][5*C+c]=ak2;
    s_part[g][6*C+c]=ab;
    __syncthreads();

    if (t < C) {
        float r[7];
#pragma unroll
        for (int j = 0; j < 7; ++j)
            r[j] = (s_part[0][j*C+t] + s_part[1][j*C+t])
                 + (s_part[2][j*C+t] + s_part[3][j*C+t]);
        g_Wqa[t] = r[0]*LOG2E; g_Wqa[C+t] = r[1]*LOG2E; g_Wqa[2*C+t] = r[2]*LOG2E;
        g_Wka[t] = r[3]*LOG2E; g_Wka[C+t] = r[4]*LOG2E; g_Wka[2*C+t] = r[5]*LOG2E;
        g_bqa[t] = (r[6] + ba[t]) * LOG2E;
    }
}

// ---------------------------------------------------------------------------
// Streaming projections: blocks [0,512) anchors, [512,1024) neighbors,
// 32 rows per block, 256 threads. anchors: g_QA = EQ = exp2(qa);
// neighbors: g_KN = [EK = exp2(-ka) | ND].
// ---------------------------------------------------------------------------
__global__ void __launch_bounds__(256)
proj_kernel(const float* __restrict__ anchor,
            const float* __restrict__ neighbor,
            const float* __restrict__ Wd,
            const float* __restrict__ bd)
{
    constexpr int TR = 32;
    __shared__ float p_s[TR * 3];

    const bool AN = blockIdx.x < 512;
    const int  base_row = (AN ? blockIdx.x : blockIdx.x - 512) * TR;
    const float* xyz = AN ? anchor : neighbor;
    const int t = threadIdx.x;

    if (t < TR * 3) p_s[t] = xyz[(size_t)base_row * 3 + t];
    __syncthreads();

    const int c = t & 127;
    const int h = t >> 7;
    const float* WA = AN ? g_Wqa : g_Wka;
    const float wax = WA[c], way = WA[C + c], waz = WA[2*C + c];
    const float wdx = Wd[c], wdy = Wd[C + c], wdz = Wd[2*C + c];
    const float ab = AN ? g_bqa[c] : 0.0f;
    const float db = AN ? bd[c]    : 0.0f;

#pragma unroll
    for (int r = 0; r < 16; ++r) {
        const int rr = h * 16 + r;
        const float x = p_s[rr*3], y = p_s[rr*3+1], z = p_s[rr*3+2];
        const float a = ab + x*wax + y*way + z*waz;
        const float d = db + x*wdx + y*wdy + z*wdz;
        const int row = base_row + rr;
        if (AN) {
            g_QA[(size_t)row * C + c] = ex2f(a);            // EQ factor
            g_AD[(size_t)row * C + c] = d;
        } else {
            g_KN[(size_t)row * (2*C) + c]     = ex2f(-a);   // EK factor
            g_KN[(size_t)row * (2*C) + C + c] = d;
        }
    }
}

// ---------------------------------------------------------------------------
// Grid build: one block per (set, batch). 512 threads, 4096 points.
// Emits g_pts: cell-sorted float4(x, y, z, local_idx).
// ---------------------------------------------------------------------------
__global__ void __launch_bounds__(512)
gridbuild_kernel(const float* __restrict__ anchor,
                 const float* __restrict__ neighbor)
{
    __shared__ int s_cnt [NC];
    __shared__ int s_scan[NC];
    __shared__ int s_cur [NC];
    __shared__ int s_cell[4096];

    const int bi  = blockIdx.x;          // set*4 + b
    const int set = bi >> 2;
    const int b   = bi & 3;
    const float* pts = (set ? neighbor : anchor) + (size_t)b * 4096 * 3;
    const int t = threadIdx.x;

    s_cnt[t] = 0;
    __syncthreads();

#pragma unroll
    for (int r = 0; r < 8; ++r) {
        const int i = t + r * 512;
        const float x = pts[i*3], y = pts[i*3+1], z = pts[i*3+2];
        int cx, cy, cz; cell_coords(x, y, z, cx, cy, cz);
        const int c = cz*64 + cy*8 + cx;
        s_cell[i] = c;
        atomicAdd(&s_cnt[c], 1);
    }
    __syncthreads();

    const int cval = s_cnt[t];
    s_scan[t] = cval;
    __syncthreads();
    for (int off = 1; off < NC; off <<= 1) {
        const int v = (t >= off) ? s_scan[t - off] : 0;
        __syncthreads();
        s_scan[t] += v;
        __syncthreads();
    }
    const int start = s_scan[t] - cval;
    g_cnt  [bi*NC + t] = cval;
    g_start[bi*NC + t] = start;
    s_cur[t] = start;
    __syncthreads();

#pragma unroll
    for (int r = 0; r < 8; ++r) {
        const int i = t + r * 512;
        const float x = pts[i*3], y = pts[i*3+1], z = pts[i*3+2];  // L1 hit
        const int slot = atomicAdd(&s_cur[s_cell[i]], 1);
        g_pts[bi*4096 + slot] = make_float4(x, y, z, __int_as_float(i));
    }
}

// ---------------------------------------------------------------------------
// Merged ball query + attention (round-15 body — 59.9us config, unchanged).
// Phase 0: lanes 0-8 fetch the 9 (z,y) span descriptors in parallel.
// Phase 1: scan spans of g_pts (coalesced float4), collect hits.
// Phase 2: slot selection (fast path hcnt<=32; slow path warp rank-sort).
// Phase 3: attention over take (x4-rounded; dup slots harmless under max).
//          s = dot(EQ, EK_row) via FMA chain; EQ deferred to epilogue.
// ---------------------------------------------------------------------------
__global__ void __launch_bounds__(256)
ballattn_kernel(float* __restrict__ out)
{
    constexpr unsigned FULL = 0xffffffffu;
    constexpr int CAP = 128;
    __shared__ int hbuf[8][CAP];
    __shared__ int sorted[8][KNN];

    const int warp = threadIdx.x >> 5;
    const int lane = threadIdx.x & 31;
    const int p    = blockIdx.x * 8 + warp;      // cell-sorted anchor position
    const int b    = p >> 12;

    const float4 a4 = g_pts[p];
    const float ax = a4.x, ay = a4.y, az = a4.z;
    const int row  = (b << 12) + __float_as_int(a4.w);
    int cx, cy, cz; cell_coords(ax, ay, az, cx, cy, cz);

    const int nbase = (B + b) * NC;
    const float4* cand = g_pts + (B + b) * 4096;

    const int x0 = max(cx - 1, 0), x1 = min(cx + 1, GC - 1);

    // --- Phase 0: parallel span-descriptor fetch (lanes 0..8) ---
    int stv = 0, env = 0;
    if (lane < 9) {
        const int z = cz - 1 + lane / 3;
        const int y = cy - 1 + lane % 3;
        if ((unsigned)z < (unsigned)GC && (unsigned)y < (unsigned)GC) {
            const int cA = nbase + z*64 + y*8 + x0;
            const int cB = nbase + z*64 + y*8 + x1;
            stv = g_start[cA];
            env = g_start[cB] + g_cnt[cB];
        }
    }

    // --- Phase 1: collect hits ---
    int hcnt = 0;
#pragma unroll
    for (int i = 0; i < 9; ++i) {
        const int st = __shfl_sync(FULL, stv, i);
        const int en = __shfl_sync(FULL, env, i);
        for (int j = st; j < en; j += 32) {
            const int q = j + lane;
            int m = 0; bool hit = false;
            if (q < en) {
                const float4 c4 = cand[q];       // coalesced LDG.128
                const float fx = c4.x - ax;
                const float fy = c4.y - ay;
                const float fz = c4.z - az;
                hit = (fx*fx + fy*fy + fz*fz) < RAD2;
                m = __float_as_int(c4.w);
            }
            const unsigned mk = __ballot_sync(FULL, hit);
            if (hit) {
                const int pos = hcnt + __popc(mk & ((1u << lane) - 1u));
                if (pos < CAP) hbuf[warp][pos] = m;
            }
            hcnt += __popc(mk);
        }
    }
    __syncwarp(FULL);

    // --- Phase 2: slot selection (lane k -> m_k) ---
    int my_m;
    if (hcnt <= KNN) {
        const int v = (lane < hcnt) ? hbuf[warp][lane] : 0x7fffffff;
        const int mn = redux_min_s32(v);
        my_m = (lane < hcnt) ? v : ((hcnt > 0) ? mn : 0);
    } else {
        const int n = min(hcnt, CAP);
        const int rounds = (n + 31) >> 5;
        int v[4], rk[4];
#pragma unroll
        for (int r = 0; r < 4; ++r) {
            const int i = lane + 32*r;
            v[r]  = (i < n) ? hbuf[warp][i] : 0x7fffffff;
            rk[r] = 0;
        }
        for (int step = 0; step < 32; ++step) {
#pragma unroll
            for (int s = 0; s < 4; ++s) {
                if (s < rounds) {
                    const int u = __shfl_sync(FULL, v[s], step);
#pragma unroll
                    for (int r = 0; r < 4; ++r)
                        if (r < rounds) rk[r] += (u < v[r]);
                }
            }
        }
#pragma unroll
        for (int r = 0; r < 4; ++r) {
            const int i = lane + 32*r;
            if (i < n && rk[r] < KNN) sorted[warp][rk[r]] = v[r];
        }
        __syncwarp(FULL);
        my_m = sorted[warp][lane];
    }

    // Distinct slots, rounded up to a multiple of 4 (dups harmless under max).
    const int t0   = (hcnt == 0) ? 1 : min(hcnt, KNN);
    const int take = min((t0 + 3) & ~3, KNN);

    // --- Phase 3: attention ---
    const float4 eqv = ((const float4*)(g_QA + (size_t)row * C))[lane];  // EQ
    const float4 ad  = ((const float4*)(g_AD + (size_t)row * C))[lane];
    const float* KNb = g_KN + (size_t)b * MPTS * (2*C);

    float4 o = make_float4(-3.4e38f, -3.4e38f, -3.4e38f, -3.4e38f);

    for (int k = 0; k < take; k += 4) {
#pragma unroll
        for (int u = 0; u < 4; ++u) {
            const int m = __shfl_sync(FULL, my_m, k + u);
            const float4* base = (const float4*)(KNb + (size_t)m * (2*C));
            const float4 kv = base[lane];        // EK factors
            const float4 nv = base[32 + lane];   // ND

            float s = fmaf(eqv.x, kv.x,
                      fmaf(eqv.y, kv.y,
                      fmaf(eqv.z, kv.z, eqv.w * kv.w)));
#pragma unroll
            for (int off = 16; off; off >>= 1)
                s += __shfl_xor_sync(FULL, s, off);

            const float inv = rcpf(s);
            o.x = fmaxf(o.x, (ad.x - nv.x) * kv.x * inv);
            o.y = fmaxf(o.y, (ad.y - nv.y) * kv.y * inv);
            o.z = fmaxf(o.z, (ad.z - nv.z) * kv.z * inv);
            o.w = fmaxf(o.w, (ad.w - nv.w) * kv.w * inv);
        }
    }

    o.x *= eqv.x; o.y *= eqv.y; o.z *= eqv.z; o.w *= eqv.w;
    ((float4*)(out + (size_t)row * C))[lane] = o;
}

// ---------------------------------------------------------------------------
// Launch graph:
//   side : fold(2us) -> proj(8us) ──┐
//   main : gridbuild(5us) ──────────┴→ merged ballattn
// fold feeds only proj; gridbuild feeds only ballattn's ball phase.
// ---------------------------------------------------------------------------
extern "C" void kernel_launch(void* const* d_in, const int* in_sizes, int n_in,
                              void* d_out, int out_size)
{
    const float* anchor   = (const float*)d_in[0];
    const float* neighbor = (const float*)d_in[1];
    const float* Wq = (const float*)d_in[2];
    const float* bq = (const float*)d_in[3];
    const float* Wk = (const float*)d_in[4];
    const float* bk = (const float*)d_in[5];
    const float* Wd = (const float*)d_in[6];
    const float* bd = (const float*)d_in[7];
    const float* Wa = (const float*)d_in[8];
    const float* ba = (const float*)d_in[9];
    float* out = (float*)d_out;

    static cudaStream_t s_side = nullptr;
    static cudaEvent_t  e_fork = nullptr, e_join = nullptr;
    if (s_side == nullptr) {
        cudaStreamCreateWithFlags(&s_side, cudaStreamNonBlocking);
        cudaEventCreateWithFlags(&e_fork, cudaEventDisableTiming);
        cudaEventCreateWithFlags(&e_join, cudaEventDisableTiming);
    }

    cudaEventRecord(e_fork, 0);
    cudaStreamWaitEvent(s_side, e_fork, 0);
    fold_kernel<<<1, 512, 0, s_side>>>(Wq, bq, Wk, bk, Wa, ba);
    proj_kernel<<<1024, 256, 0, s_side>>>(anchor, neighbor, Wd, bd);
    cudaEventRecord(e_join, s_side);

    gridbuild_kernel<<<8, 512>>>(anchor, neighbor);

    cudaStreamWaitEvent(0, e_join, 0);
    ballattn_kernel<<<2048, 256>>>(out);
}